// round 7
// baseline (speedup 1.0000x reference)
#include <cuda_runtime.h>

// PatchExtractor3d: out[b, c*27 + i*9 + j*3 + l, d, h, w] = xpad[b, c, d+i, h+j, w+l]
// x [2,3,32,128,128] fp32 -> out [2,81,32,128,128] fp32, pad=1, K=3.
//
// SCATTER formulation: one warp per INPUT row. Read the 512B row once
// (LDG.128), build the 3 w-shift variants via shfl, then store to all valid
// (i,j,l) output rows (<=27 STG.128). Output rows whose source is padding
// (~4%) are zero-filled by dedicated tail warps in the same launch.
// This cuts L2->L1 read traffic 27x vs the gather kernel (340MB -> 12.6MB).

static constexpr int B_  = 2;
static constexpr int C_  = 3;
static constexpr int D_  = 32;
static constexpr int H_  = 128;
static constexpr int W_  = 128;
static constexpr int COUT = C_ * 27;                  // 81

static constexpr int IN_ROWS  = B_ * C_ * D_ * H_;    // 24576 scatter warps
// zero rows: din-invalid planes: 2 cases x b2 x c3 x (j,l)9 = 108 planes x 128 h
static constexpr int ZERO_A   = 108 * H_;             // 13824
// hin-invalid rows: 2 cases x b2 x c3 x i3 x l3 x d32
static constexpr int ZERO_B   = 2 * B_ * C_ * 3 * 3 * D_;  // 3456
static constexpr int TOT_WARPS = IN_ROWS + ZERO_A + ZERO_B; // 41856
static constexpr int BLOCKS    = TOT_WARPS / 8;       // 5232 (exact)

__global__ __launch_bounds__(256)
void patch3d_scatter(const float* __restrict__ x, float* __restrict__ out) {
    const int gw   = blockIdx.x * 8 + (threadIdx.x >> 5);
    const int lane = threadIdx.x & 31;
    float4* __restrict__ o4 = reinterpret_cast<float4*>(out);

    if (gw < IN_ROWS) {
        // ---- scatter warp: input row (b, c, din, hin) = linear gw ----
        const int hin = gw & (H_ - 1);
        const int din = (gw >> 7) & (D_ - 1);
        const int bc  = gw >> 12;          // b*3 + c, 0..5
        const int c   = bc % 3;
        const int b   = bc / 3;

        const float4 cur =
            __ldg(reinterpret_cast<const float4*>(x) + (size_t)gw * 32 + lane);

        // w-shift variants: out[w] = in[w + l - 1]
        float4 v0, v2;
        const float4 v1 = cur;                       // l=1 identity
        {
            const float pw = __shfl_up_sync(0xffffffffu, cur.w, 1);
            v0.x = (lane == 0) ? 0.f : pw;           // l=0: in[w-1]
            v0.y = cur.x; v0.z = cur.y; v0.w = cur.z;
            const float nx = __shfl_down_sync(0xffffffffu, cur.x, 1);
            v2.x = cur.y; v2.y = cur.z; v2.z = cur.w; // l=2: in[w+1]
            v2.w = (lane == 31) ? 0.f : nx;
        }

        // R(s,i,j) = base + s*4096 - i*128 - j   (row units; 4096 = D-plane rows? no: 32*128)
        // base = (b*81 + c*27)*4096 + (din+1)*128 + (hin+1)
        const long base = (long)(b * COUT + c * 27) * 4096
                        + (long)(din + 1) * 128 + (hin + 1);
        float4* const p = o4 + base * 32 + lane;

        const bool iv[3] = { din <= D_ - 2, true, din >= 1 };   // d = din+1-i valid
        const bool jv[3] = { hin <= H_ - 2, true, hin >= 1 };   // h = hin+1-j valid

        #pragma unroll
        for (int i = 0; i < 3; ++i) {
            if (!iv[i]) continue;                    // warp-uniform
            #pragma unroll
            for (int j = 0; j < 3; ++j) {
                if (!jv[j]) continue;                // warp-uniform
                const long off = ((long)(i * 9 + j * 3) * 4096 - i * 128 - j) * 32;
                float4* const q = p + off;
                __stcs(q,                 v0);       // l=0
                __stcs(q + 1L * 4096 * 32, v1);      // l=1
                __stcs(q + 2L * 4096 * 32, v2);      // l=2
            }
        }
    } else {
        // ---- zero warp: write one all-zero output row ----
        const int z = gw - IN_ROWS;
        long R;
        if (z < ZERO_A) {
            // din-invalid planes: (i=0,d=0) or (i=2,d=31), all h
            const int h     = z & (H_ - 1);
            const int pl    = z >> 7;                // 0..107
            const int icase = pl / 54;               // 0:(i=0,d=0) 1:(i=2,d=31)
            const int p2    = pl - icase * 54;
            const int b     = p2 / 27;
            const int rem   = p2 - b * 27;
            const int c     = rem / 9;
            const int jl    = rem - c * 9;           // j*3 + l
            const int i     = icase ? 2 : 0;
            const int d     = icase ? (D_ - 1) : 0;
            const int co    = c * 27 + i * 9 + jl;
            R = ((long)(b * COUT + co) * D_ + d) * H_ + h;
        } else {
            // hin-invalid rows: (j=0,h=0) or (j=2,h=127), all valid-d planes
            int t = z - ZERO_A;                      // 0..3455
            const int jcase = t / 1728;
            t -= jcase * 1728;
            const int d  = t & (D_ - 1);
            const int t2 = t >> 5;                   // 0..53 = l + 3i + 9c + 27b
            const int l  = t2 % 3;
            const int i  = (t2 / 3) % 3;
            const int c  = (t2 / 9) % 3;
            const int b  = t2 / 27;
            const int j  = jcase ? 2 : 0;
            const int h  = jcase ? (H_ - 1) : 0;
            const int co = c * 27 + i * 9 + j * 3 + l;
            R = ((long)(b * COUT + co) * D_ + d) * H_ + h;
        }
        __stcs(o4 + R * 32 + lane, make_float4(0.f, 0.f, 0.f, 0.f));
    }
}

extern "C" void kernel_launch(void* const* d_in, const int* in_sizes, int n_in,
                              void* d_out, int out_size) {
    const float* x = (const float*)d_in[0];
    float* out = (float*)d_out;
    (void)in_sizes; (void)n_in; (void)out_size;

    patch3d_scatter<<<BLOCKS, 256>>>(x, out);
}